// round 13
// baseline (speedup 1.0000x reference)
#include <cuda_runtime.h>

// Float32HardwareSurrogate — persistent grid-stride version of the R7 kernel
// (best ncu/bench so far). Exact-fit grid (SMs x 5 blocks) runs ONE wave;
// each warp loops over ~11 warp-tasks of 32 images. Eliminates ~10 wave
// transitions and amortizes the per-block prologue (weight loads + permute).
//
// Per-task compute (identical numerics to R7):
// Coalesced float4 loads (idx = lane + 32k) put one complete image per
// 16-lane group per iteration: lane e holds float4 element e of image
// 2k+(lane>>4). Element e -> quadrant q=((e>>3)<<1)|(e&1), row rr=(e>>1)&3.
// Stage 1 reduce-scatter (xor4 x2, xor2) -> scalar c[K], K=q*4+rr.
// Stage 2 T=clip(relu(c)/64)*Wl[K]; reduce-scatter (xor8 x2, xor4, xor2,
// xor1) -> output comp ncomp; 8 lanes store 32 contiguous bytes.
// Weights pre-permuted per lane (pos p = channel rr^p / output ncomp^p) so
// all scatter steps are unconditionally keep(x,y)/send(z,w) — SEL-free.

#define THREADS 256
#define WARPS_PER_BLOCK 8
#define IMGS_PER_WARP 32
#define BLOCKS_PER_SM 5

// XOR-permute float4 components: result pos p = w[bits ^ p]. Prologue-only.
__device__ __forceinline__ float4 xorperm(float4 w, int bits) {
    float t;
    if (bits & 2) { t = w.x; w.x = w.z; w.z = t; t = w.y; w.y = w.w; w.w = t; }
    if (bits & 1) { t = w.x; w.x = w.y; w.y = t; t = w.z; w.z = w.w; w.w = t; }
    return w;
}

__global__ void __launch_bounds__(THREADS, BLOCKS_PER_SM)  // 51-reg cap
surrogate_kernel(const float* __restrict__ img1,
                 const float* __restrict__ img2,
                 const float* __restrict__ Wc,
                 const float* __restrict__ Wl,
                 float* __restrict__ out,
                 int nimg)
{
    const int lane = threadIdx.x & 31;
    const int warp = threadIdx.x >> 5;

    const int e     = lane & 15;
    const int g     = lane >> 4;
    const int rr    = (e >> 1) & 3;
    const int q     = ((e >> 3) << 1) | (e & 1);
    const int K     = q * 4 + rr;
    const int ncomp = 2 * ((e >> 3) & 1) + ((e >> 2) & 1);
    const bool do_store = ((e & 3) == 0);

    // One-time weight prologue (amortized over ~11 tasks).
    const float4* __restrict__ Wc4 = (const float4*)Wc;
    const float4* __restrict__ Wl4 = (const float4*)Wl;
    const float4 wc0 = xorperm(Wc4[rr * 4 + 0], rr);
    const float4 wc1 = xorperm(Wc4[rr * 4 + 1], rr);
    const float4 wc2 = xorperm(Wc4[rr * 4 + 2], rr);
    const float4 wc3 = xorperm(Wc4[rr * 4 + 3], rr);
    const float4 wl  = xorperm(Wl4[K], ncomp);

    const float inv64 = 0.015625f;
    const unsigned FULL = 0xffffffffu;

    const long nwtasks = (2L * (long)nimg) / IMGS_PER_WARP;  // warp-tasks total
    const long stride  = (long)gridDim.x * WARPS_PER_BLOCK;
    long task = (long)blockIdx.x * WARPS_PER_BLOCK + warp;

    #define COMPUTE_STORE(v_, k_)                                              \
    do {                                                                       \
        float4 P;                                                              \
        P.x = (v_).x * wc0.x; P.y = (v_).x * wc0.y;                            \
        P.z = (v_).x * wc0.z; P.w = (v_).x * wc0.w;                            \
        P.x = fmaf((v_).y, wc1.x, P.x); P.y = fmaf((v_).y, wc1.y, P.y);        \
        P.z = fmaf((v_).y, wc1.z, P.z); P.w = fmaf((v_).y, wc1.w, P.w);        \
        P.x = fmaf((v_).z, wc2.x, P.x); P.y = fmaf((v_).z, wc2.y, P.y);        \
        P.z = fmaf((v_).z, wc2.z, P.z); P.w = fmaf((v_).z, wc2.w, P.w);        \
        P.x = fmaf((v_).w, wc3.x, P.x); P.y = fmaf((v_).w, wc3.y, P.y);        \
        P.z = fmaf((v_).w, wc3.z, P.z); P.w = fmaf((v_).w, wc3.w, P.w);        \
        float A  = P.x + __shfl_xor_sync(FULL, P.z, 4);                        \
        float Bv = P.y + __shfl_xor_sync(FULL, P.w, 4);                        \
        float c1 = A   + __shfl_xor_sync(FULL, Bv,  2);                        \
        float cv = fminf(fmaxf(c1, 0.0f) * inv64, 127.0f);                     \
        float Tx = cv * wl.x, Ty = cv * wl.y;                                  \
        float Tz = cv * wl.z, Tw = cv * wl.w;                                  \
        float A2 = Tx + __shfl_xor_sync(FULL, Tz, 8);                          \
        float B2 = Ty + __shfl_xor_sync(FULL, Tw, 8);                          \
        float sc = A2 + __shfl_xor_sync(FULL, B2, 4);                          \
        sc += __shfl_xor_sync(FULL, sc, 2);                                    \
        sc += __shfl_xor_sync(FULL, sc, 1);                                    \
        float o = fminf(fmaxf(sc * inv64, -128.0f), 127.0f);                   \
        if (do_store) __stcs(outp + 8 * (k_), o);                              \
    } while (0)

    for (; task < nwtasks; task += stride) {
        const long g0 = task * IMGS_PER_WARP;
        // nimg is a multiple of 32 -> task never straddles img1/img2.
        const float4* __restrict__ src = (const float4*)(
            (g0 < (long)nimg) ? (img1 + g0 * 64)
                              : (img2 + (g0 - (long)nimg) * 64));
        float* __restrict__ outp = out + (g0 + g) * 4 + ncomp;

        // Ring software pipeline, window 4.
        float4 v[4];
        #pragma unroll
        for (int k = 0; k < 4; ++k)
            v[k] = __ldcs(&src[lane + 32 * k]);

        #pragma unroll
        for (int k = 0; k < 16; ++k) {
            float4 cur = v[k & 3];
            if (k < 12)
                v[k & 3] = __ldcs(&src[lane + 32 * (k + 4)]);
            COMPUTE_STORE(cur, k);
        }
    }

    #undef COMPUTE_STORE
}

extern "C" void kernel_launch(void* const* d_in, const int* in_sizes, int n_in,
                              void* d_out, int out_size) {
    const float* img1 = (const float*)d_in[0];
    const float* img2 = (const float*)d_in[1];
    const float* Wc   = (const float*)d_in[2];
    const float* Wl   = (const float*)d_in[3];
    float* out        = (float*)d_out;

    int nimg = in_sizes[0] / 64;                       // B
    long total_imgs = 2L * (long)nimg;
    long total_warps = (total_imgs + IMGS_PER_WARP - 1) / IMGS_PER_WARP;

    int sms = 148;
    cudaDeviceGetAttribute(&sms, cudaDevAttrMultiProcessorCount, 0);
    long nblocks = (long)sms * BLOCKS_PER_SM;          // exact-fit: one wave
    long max_blocks = (total_warps + WARPS_PER_BLOCK - 1) / WARPS_PER_BLOCK;
    if (nblocks > max_blocks) nblocks = max_blocks;

    surrogate_kernel<<<(int)nblocks, THREADS>>>(img1, img2, Wc, Wl, out, nimg);
}

// round 14
// speedup vs baseline: 1.0914x; 1.0914x over previous
#include <cuda_runtime.h>

// Float32HardwareSurrogate — R7 structure with 64-image warp-tasks.
// Longer tasks cut the end-of-task load-pipeline drain from 25% to 12.5% of
// iterations and halve per-block prologue count; grid stays multi-wave
// (~5.5 waves) so fresh blocks cover residual drains (the R12 persistent
// single-wave variant failed precisely for lack of this).
//
// Per-iteration compute (identical numerics to R7):
// Coalesced float4 loads (idx = lane + 32k) put one complete image per
// 16-lane group per iteration: lane e holds float4 element e of image
// 2k+(lane>>4). Element e -> quadrant q=((e>>3)<<1)|(e&1), row rr=(e>>1)&3.
// Stage 1 reduce-scatter (xor4 x2, xor2) -> scalar c[K], K=q*4+rr.
// Stage 2 T=clip(relu(c)/64)*Wl[K]; reduce-scatter (xor8 x2, xor4, xor2,
// xor1) -> output comp ncomp; 8 lanes store 32 contiguous bytes.
// Weights pre-permuted per lane (pos p = channel rr^p / output ncomp^p) so
// all scatter steps are unconditionally keep(x,y)/send(z,w) — SEL-free.

#define THREADS 256
#define WARPS_PER_BLOCK 8
#define IMGS_PER_WARP 64
#define ITERS 32                 // IMGS_PER_WARP / 2
#define PREFETCH_LAST 28         // ITERS - window

// XOR-permute float4 components: result pos p = w[bits ^ p]. Prologue-only.
__device__ __forceinline__ float4 xorperm(float4 w, int bits) {
    float t;
    if (bits & 2) { t = w.x; w.x = w.z; w.z = t; t = w.y; w.y = w.w; w.w = t; }
    if (bits & 1) { t = w.x; w.x = w.y; w.y = t; t = w.z; w.z = w.w; w.w = t; }
    return w;
}

__global__ void __launch_bounds__(THREADS, 5)   // 51-reg cap -> 40 warps/SM
surrogate_kernel(const float* __restrict__ img1,
                 const float* __restrict__ img2,
                 const float* __restrict__ Wc,
                 const float* __restrict__ Wl,
                 float* __restrict__ out,
                 int nimg)
{
    const int lane = threadIdx.x & 31;
    const int warp = threadIdx.x >> 5;
    const long wg  = (long)blockIdx.x * WARPS_PER_BLOCK + warp;
    const long g0  = wg * IMGS_PER_WARP;
    const long total = 2L * (long)nimg;
    if (g0 >= total) return;

    // nimg is a multiple of 64 -> task never straddles img1/img2.
    const float4* __restrict__ src = (const float4*)(
        (g0 < (long)nimg) ? (img1 + g0 * 64)
                          : (img2 + (g0 - (long)nimg) * 64));

    const int e     = lane & 15;
    const int g     = lane >> 4;
    const int rr    = (e >> 1) & 3;
    const int q     = ((e >> 3) << 1) | (e & 1);
    const int K     = q * 4 + rr;
    const int ncomp = 2 * ((e >> 3) & 1) + ((e >> 2) & 1);
    const bool do_store = ((e & 3) == 0);

    // Vector weight loads + one-time per-lane XOR permutation.
    const float4* __restrict__ Wc4 = (const float4*)Wc;
    const float4* __restrict__ Wl4 = (const float4*)Wl;
    const float4 wc0 = xorperm(Wc4[rr * 4 + 0], rr);
    const float4 wc1 = xorperm(Wc4[rr * 4 + 1], rr);
    const float4 wc2 = xorperm(Wc4[rr * 4 + 2], rr);
    const float4 wc3 = xorperm(Wc4[rr * 4 + 3], rr);
    const float4 wl  = xorperm(Wl4[K], ncomp);

    const float inv64 = 0.015625f;
    const unsigned FULL = 0xffffffffu;
    float* __restrict__ outp = out + (g0 + g) * 4 + ncomp;

    #define COMPUTE_STORE(v_, k_)                                              \
    do {                                                                       \
        float4 P;                                                              \
        P.x = (v_).x * wc0.x; P.y = (v_).x * wc0.y;                            \
        P.z = (v_).x * wc0.z; P.w = (v_).x * wc0.w;                            \
        P.x = fmaf((v_).y, wc1.x, P.x); P.y = fmaf((v_).y, wc1.y, P.y);        \
        P.z = fmaf((v_).y, wc1.z, P.z); P.w = fmaf((v_).y, wc1.w, P.w);        \
        P.x = fmaf((v_).z, wc2.x, P.x); P.y = fmaf((v_).z, wc2.y, P.y);        \
        P.z = fmaf((v_).z, wc2.z, P.z); P.w = fmaf((v_).z, wc2.w, P.w);        \
        P.x = fmaf((v_).w, wc3.x, P.x); P.y = fmaf((v_).w, wc3.y, P.y);        \
        P.z = fmaf((v_).w, wc3.z, P.z); P.w = fmaf((v_).w, wc3.w, P.w);        \
        float A  = P.x + __shfl_xor_sync(FULL, P.z, 4);                        \
        float Bv = P.y + __shfl_xor_sync(FULL, P.w, 4);                        \
        float c1 = A   + __shfl_xor_sync(FULL, Bv,  2);                        \
        float cv = fminf(fmaxf(c1, 0.0f) * inv64, 127.0f);                     \
        float Tx = cv * wl.x, Ty = cv * wl.y;                                  \
        float Tz = cv * wl.z, Tw = cv * wl.w;                                  \
        float A2 = Tx + __shfl_xor_sync(FULL, Tz, 8);                          \
        float B2 = Ty + __shfl_xor_sync(FULL, Tw, 8);                          \
        float sc = A2 + __shfl_xor_sync(FULL, B2, 4);                          \
        sc += __shfl_xor_sync(FULL, sc, 2);                                    \
        sc += __shfl_xor_sync(FULL, sc, 1);                                    \
        float o = fminf(fmaxf(sc * inv64, -128.0f), 127.0f);                   \
        if (do_store) __stcs(outp + 8 * (k_), o);                              \
    } while (0)

    // Ring software pipeline, window 4, across 32 iterations (64 images).
    float4 v[4];
    #pragma unroll
    for (int k = 0; k < 4; ++k)
        v[k] = __ldcs(&src[lane + 32 * k]);

    #pragma unroll
    for (int k = 0; k < ITERS; ++k) {
        float4 cur = v[k & 3];
        if (k < PREFETCH_LAST)
            v[k & 3] = __ldcs(&src[lane + 32 * (k + 4)]);
        COMPUTE_STORE(cur, k);
    }

    #undef COMPUTE_STORE
}

extern "C" void kernel_launch(void* const* d_in, const int* in_sizes, int n_in,
                              void* d_out, int out_size) {
    const float* img1 = (const float*)d_in[0];
    const float* img2 = (const float*)d_in[1];
    const float* Wc   = (const float*)d_in[2];
    const float* Wl   = (const float*)d_in[3];
    float* out        = (float*)d_out;

    int nimg = in_sizes[0] / 64;                       // B
    long total_imgs = 2L * (long)nimg;
    long total_warps = (total_imgs + IMGS_PER_WARP - 1) / IMGS_PER_WARP;
    int nblocks = (int)((total_warps + WARPS_PER_BLOCK - 1) / WARPS_PER_BLOCK);

    surrogate_kernel<<<nblocks, THREADS>>>(img1, img2, Wc, Wl, out, nimg);
}

// round 15
// speedup vs baseline: 1.1136x; 1.0203x over previous
#include <cuda_runtime.h>

// Float32HardwareSurrogate — R7 kernel (best bench+ncu) with a reordered
// prologue: the 4 data-window LDG.128s issue BEFORE the weight loads, so each
// block's DRAM stream starts ~200 cycles earlier (weight L2-hit latency and
// the xorperm SELs overlap the in-flight data loads). Branchless src select,
// no early-return guard (grid exactly covers the work), unsigned indexing.
//
// Hot-loop (identical numerics to R7):
// Coalesced float4 loads (idx = lane + 32k) put one complete image per
// 16-lane group per iteration: lane e holds float4 element e of image
// 2k+(lane>>4). Element e -> quadrant q=((e>>3)<<1)|(e&1), row rr=(e>>1)&3.
// Stage 1 reduce-scatter (xor4 x2, xor2) -> scalar c[K], K=q*4+rr.
// Stage 2 T=clip(relu(c)/64)*Wl[K]; reduce-scatter (xor8 x2, xor4, xor2,
// xor1) -> output comp ncomp; 8 lanes store 32 contiguous bytes.
// Weights pre-permuted per lane (pos p = channel rr^p / output ncomp^p) so
// all scatter steps are unconditionally keep(x,y)/send(z,w) — SEL-free.

#define THREADS 256
#define WARPS_PER_BLOCK 8
#define IMGS_PER_WARP 32

// XOR-permute float4 components: result pos p = w[bits ^ p]. Prologue-only.
__device__ __forceinline__ float4 xorperm(float4 w, int bits) {
    float t;
    if (bits & 2) { t = w.x; w.x = w.z; w.z = t; t = w.y; w.y = w.w; w.w = t; }
    if (bits & 1) { t = w.x; w.x = w.y; w.y = t; t = w.z; w.z = w.w; w.w = t; }
    return w;
}

__global__ void __launch_bounds__(THREADS, 5)   // 51-reg cap -> 40 warps/SM
surrogate_kernel(const float* __restrict__ img1,
                 const float* __restrict__ img2,
                 const float* __restrict__ Wc,
                 const float* __restrict__ Wl,
                 float* __restrict__ out,
                 unsigned nimg)
{
    const unsigned lane = threadIdx.x & 31u;
    const unsigned warp = threadIdx.x >> 5;
    const unsigned wg   = blockIdx.x * WARPS_PER_BLOCK + warp;
    const unsigned g0   = wg * IMGS_PER_WARP;   // fits: 2^21 images max here

    // Branchless source select (nimg is a multiple of 32: no straddle).
    const bool second = (g0 >= nimg);
    const float* base = second ? img2 : img1;
    const unsigned gl = second ? (g0 - nimg) : g0;
    const float4* __restrict__ src = (const float4*)(base + (size_t)gl * 64u);

    // ---- data loads FIRST: start the DRAM stream immediately ----
    float4 v[4];
    #pragma unroll
    for (int k = 0; k < 4; ++k)
        v[k] = __ldcs(&src[lane + 32u * k]);

    // ---- per-lane constants + weight loads (overlap the data loads) ----
    const unsigned e     = lane & 15u;
    const unsigned g     = lane >> 4;
    const int rr    = (int)((e >> 1) & 3u);
    const int q     = (int)(((e >> 3) << 1) | (e & 1u));
    const int K     = q * 4 + rr;
    const int ncomp = (int)(2u * ((e >> 3) & 1u) + ((e >> 2) & 1u));
    const bool do_store = ((e & 3u) == 0u);

    const float4* __restrict__ Wc4 = (const float4*)Wc;
    const float4* __restrict__ Wl4 = (const float4*)Wl;
    const float4 wc0 = xorperm(Wc4[rr * 4 + 0], rr);
    const float4 wc1 = xorperm(Wc4[rr * 4 + 1], rr);
    const float4 wc2 = xorperm(Wc4[rr * 4 + 2], rr);
    const float4 wc3 = xorperm(Wc4[rr * 4 + 3], rr);
    const float4 wl  = xorperm(Wl4[K], ncomp);

    const float inv64 = 0.015625f;
    const unsigned FULL = 0xffffffffu;
    float* __restrict__ outp = out + (size_t)(g0 + g) * 4u + ncomp;

    #define COMPUTE_STORE(v_, k_)                                              \
    do {                                                                       \
        float4 P;                                                              \
        P.x = (v_).x * wc0.x; P.y = (v_).x * wc0.y;                            \
        P.z = (v_).x * wc0.z; P.w = (v_).x * wc0.w;                            \
        P.x = fmaf((v_).y, wc1.x, P.x); P.y = fmaf((v_).y, wc1.y, P.y);        \
        P.z = fmaf((v_).y, wc1.z, P.z); P.w = fmaf((v_).y, wc1.w, P.w);        \
        P.x = fmaf((v_).z, wc2.x, P.x); P.y = fmaf((v_).z, wc2.y, P.y);        \
        P.z = fmaf((v_).z, wc2.z, P.z); P.w = fmaf((v_).z, wc2.w, P.w);        \
        P.x = fmaf((v_).w, wc3.x, P.x); P.y = fmaf((v_).w, wc3.y, P.y);        \
        P.z = fmaf((v_).w, wc3.z, P.z); P.w = fmaf((v_).w, wc3.w, P.w);        \
        float A  = P.x + __shfl_xor_sync(FULL, P.z, 4);                        \
        float Bv = P.y + __shfl_xor_sync(FULL, P.w, 4);                        \
        float c1 = A   + __shfl_xor_sync(FULL, Bv,  2);                        \
        float cv = fminf(fmaxf(c1, 0.0f) * inv64, 127.0f);                     \
        float Tx = cv * wl.x, Ty = cv * wl.y;                                  \
        float Tz = cv * wl.z, Tw = cv * wl.w;                                  \
        float A2 = Tx + __shfl_xor_sync(FULL, Tz, 8);                          \
        float B2 = Ty + __shfl_xor_sync(FULL, Tw, 8);                          \
        float sc = A2 + __shfl_xor_sync(FULL, B2, 4);                          \
        sc += __shfl_xor_sync(FULL, sc, 2);                                    \
        sc += __shfl_xor_sync(FULL, sc, 1);                                    \
        float o = fminf(fmaxf(sc * inv64, -128.0f), 127.0f);                   \
        if (do_store) __stcs(outp + 8 * (k_), o);                              \
    } while (0)

    // Ring software pipeline, window 4, 16 iterations (32 images).
    #pragma unroll
    for (int k = 0; k < 16; ++k) {
        float4 cur = v[k & 3];
        if (k < 12)
            v[k & 3] = __ldcs(&src[lane + 32u * (k + 4)]);
        COMPUTE_STORE(cur, k);
    }

    #undef COMPUTE_STORE
}

extern "C" void kernel_launch(void* const* d_in, const int* in_sizes, int n_in,
                              void* d_out, int out_size) {
    const float* img1 = (const float*)d_in[0];
    const float* img2 = (const float*)d_in[1];
    const float* Wc   = (const float*)d_in[2];
    const float* Wl   = (const float*)d_in[3];
    float* out        = (float*)d_out;

    unsigned nimg = (unsigned)(in_sizes[0] / 64);      // B
    long total_imgs = 2L * (long)nimg;
    long total_warps = (total_imgs + IMGS_PER_WARP - 1) / IMGS_PER_WARP;
    int nblocks = (int)((total_warps + WARPS_PER_BLOCK - 1) / WARPS_PER_BLOCK);

    surrogate_kernel<<<nblocks, THREADS>>>(img1, img2, Wc, Wl, out, nimg);
}